// round 1
// baseline (speedup 1.0000x reference)
#include <cuda_runtime.h>
#include <math.h>

#define BB 32
#define SS 4096
#define NH 8
#define HD 32
#define PD 128   // prot dim
#define MD 128   // mol dim
#define AD 256   // att dim

// Scratch (static device globals; no runtime allocation)
__device__ float g_scores[BB * SS * NH];   // [b][s][h], unscaled dot products
__device__ float g_qk[BB * NH * PD];       // [b][h][c]
__device__ float g_kb[BB * NH];
__device__ float g_U[BB * NH * PD];        // [b][h][j]
__device__ float g_M[BB * NH];             // scaled-score max over s
__device__ float g_Z[BB * NH];             // scaled-score sumexp over s
__device__ float g_wp[BB * NH * PD];       // weighted prot features (atomic accum)

// ---------------------------------------------------------------------------
// Kernel A: per-batch precompute + zero wp.  grid=32, block=256
// ---------------------------------------------------------------------------
__global__ void k_setup(const float* __restrict__ mol,
                        const float* __restrict__ Wq,  const float* __restrict__ bq,
                        const float* __restrict__ Wmv, const float* __restrict__ bmv,
                        const float* __restrict__ Wpk, const float* __restrict__ bpk,
                        const float* __restrict__ Wpo)
{
    int b = blockIdx.x, t = threadIdx.x;
    __shared__ float sm_mol[MD];
    __shared__ float sm_q[AD];
    __shared__ float sm_v[AD];

    if (t < MD) sm_mol[t] = mol[b * MD + t];
    __syncthreads();

    // mol_q / mol_v rows (t = 0..255)
    {
        float aq = bq[t], av = bmv[t];
        const float* wq = Wq  + t * MD;
        const float* wv = Wmv + t * MD;
        #pragma unroll 8
        for (int c = 0; c < MD; c++) {
            float m = sm_mol[c];
            aq += m * wq[c];
            av += m * wv[c];
        }
        sm_q[t] = aq;
        sm_v[t] = av;
    }
    __syncthreads();

    // qk[b][h][c] and U[b][h][j]; 1024 values each, 4 per thread
    #pragma unroll
    for (int k = 0; k < 4; k++) {
        int idx = t + 256 * k;
        int h = idx >> 7, c = idx & 127;
        float accq = 0.f, accu = 0.f;
        #pragma unroll
        for (int d = 0; d < HD; d++) {
            accq += Wpk[(h * HD + d) * PD + c] * sm_q[h * HD + d];
            accu += sm_v[h * HD + d] * Wpo[c * AD + h * HD + d];
        }
        g_qk[b * NH * PD + idx] = accq;
        g_U [b * NH * PD + idx] = accu;
        g_wp[b * NH * PD + idx] = 0.f;   // re-zero every launch (graph replay safe)
    }

    if (t < NH) {
        float a = 0.f;
        #pragma unroll
        for (int d = 0; d < HD; d++) a += bpk[t * HD + d] * sm_q[t * HD + d];
        g_kb[b * NH + t] = a;
    }
}

// ---------------------------------------------------------------------------
// Kernel B: scores[b,s,h] = prot[b,s,:]·qk[b,h,:] + kb[b,h]
// grid=(SS/256, BB), block=256; one thread per s position
// ---------------------------------------------------------------------------
__global__ void k_scores(const float* __restrict__ prot)
{
    int b = blockIdx.y;
    int t = threadIdx.x;
    int s = blockIdx.x * 256 + t;

    __shared__ float4 qk4[NH][PD / 4];
    __shared__ float kbs[NH];

    ((float4*)qk4)[t] = ((const float4*)(g_qk + b * NH * PD))[t];
    if (t < NH) kbs[t] = g_kb[b * NH + t];
    __syncthreads();

    float acc[NH];
    #pragma unroll
    for (int h = 0; h < NH; h++) acc[h] = kbs[h];

    const float4* p4 = (const float4*)(prot + ((size_t)b * SS + s) * PD);
    #pragma unroll 8
    for (int c4 = 0; c4 < PD / 4; c4++) {
        float4 p = p4[c4];
        #pragma unroll
        for (int h = 0; h < NH; h++) {
            float4 q = qk4[h][c4];   // broadcast across warp
            acc[h] += p.x * q.x + p.y * q.y + p.z * q.z + p.w * q.w;
        }
    }

    float4* out = (float4*)(g_scores + ((size_t)b * SS + s) * NH);
    out[0] = make_float4(acc[0], acc[1], acc[2], acc[3]);
    out[1] = make_float4(acc[4], acc[5], acc[6], acc[7]);
}

// ---------------------------------------------------------------------------
// Kernel C: per-(b,h) softmax stats over s (scaled scores).
// grid=BB*NH, block=256
// ---------------------------------------------------------------------------
__global__ void k_stats(float scale)
{
    int b = blockIdx.x >> 3, h = blockIdx.x & 7;
    int t = threadIdx.x;

    const float* sc = g_scores + (size_t)b * SS * NH + h;
    float v[16];
    float mx = -1e30f;
    #pragma unroll
    for (int k = 0; k < 16; k++) {
        v[k] = sc[(size_t)(t + 256 * k) * NH] * scale;
        mx = fmaxf(mx, v[k]);
    }

    __shared__ float redm[8];
    __shared__ float redz[8];

    #pragma unroll
    for (int o = 16; o; o >>= 1) mx = fmaxf(mx, __shfl_xor_sync(~0u, mx, o));
    if ((t & 31) == 0) redm[t >> 5] = mx;
    __syncthreads();
    if (t < 32) {
        float m2 = (t < 8) ? redm[t] : -1e30f;
        #pragma unroll
        for (int o = 4; o; o >>= 1) m2 = fmaxf(m2, __shfl_xor_sync(~0u, m2, o));
        if (t == 0) redm[0] = m2;
    }
    __syncthreads();
    mx = redm[0];

    float z = 0.f;
    #pragma unroll
    for (int k = 0; k < 16; k++) z += expf(v[k] - mx);
    #pragma unroll
    for (int o = 16; o; o >>= 1) z += __shfl_xor_sync(~0u, z, o);
    if ((t & 31) == 0) redz[t >> 5] = z;
    __syncthreads();
    if (t == 0) {
        float zz = 0.f;
        #pragma unroll
        for (int w = 0; w < 8; w++) zz += redz[w];
        g_M[b * NH + h] = mx;
        g_Z[b * NH + h] = zz;
    }
}

// ---------------------------------------------------------------------------
// Kernel D: main streaming pass.
//   per (b,s): p2m softmax over heads -> attended_prot_features output
//              m2p weights            -> avg weights + wp accumulation
// grid=(SS/128, BB), block=128
// ---------------------------------------------------------------------------
__global__ void k_main(const float* __restrict__ prot,
                       const float* __restrict__ bpo,
                       float* __restrict__ outP,
                       float* __restrict__ outA,
                       float scale)
{
    int b = blockIdx.y;
    int s0 = blockIdx.x * 128;
    int t = threadIdx.x;

    __shared__ float4 U4[NH][PD / 4];
    __shared__ float4 bpo4s[PD / 4];
    __shared__ float Ms[NH], Zs[NH];
    __shared__ float e_s[128][NH + 1];          // +1 pad: bank-conflict-free
    __shared__ float part[4][NH][PD];           // wp partials per s-chunk

    {
        const float4* gU = (const float4*)(g_U + b * NH * PD);
        ((float4*)U4)[t]       = gU[t];
        ((float4*)U4)[t + 128] = gU[t + 128];
        if (t < PD / 4) bpo4s[t] = ((const float4*)bpo)[t];
        if (t < NH) { Ms[t] = g_M[b * NH + t]; Zs[t] = g_Z[b * NH + t]; }
    }
    __syncthreads();

    int s = s0 + t;
    const float* scp = g_scores + ((size_t)b * SS + s) * NH;
    float sc[NH];
    {
        float4 sA = ((const float4*)scp)[0];
        float4 sB = ((const float4*)scp)[1];
        sc[0] = sA.x; sc[1] = sA.y; sc[2] = sA.z; sc[3] = sA.w;
        sc[4] = sB.x; sc[5] = sB.y; sc[6] = sB.z; sc[7] = sB.w;
    }

    // p2m: softmax over heads of UNSCALED scores
    float w8[NH];
    {
        float mx = sc[0];
        #pragma unroll
        for (int h = 1; h < NH; h++) mx = fmaxf(mx, sc[h]);
        float wsum = 0.f;
        #pragma unroll
        for (int h = 0; h < NH; h++) { w8[h] = expf(sc[h] - mx); wsum += w8[h]; }
        float inv = 1.f / wsum;
        #pragma unroll
        for (int h = 0; h < NH; h++) w8[h] *= inv;
    }

    // m2p: weights over s of SCALED scores (global stats)
    {
        float esum = 0.f;
        #pragma unroll
        for (int h = 0; h < NH; h++) {
            float e = expf(sc[h] * scale - Ms[h]) / Zs[h];
            e_s[t][h] = e;
            esum += e;
        }
        outA[(size_t)b * SS + s] = esum * 0.125f;   // mean over 8 heads
    }

    // attended_prot_features output row
    {
        const float4* pp = (const float4*)(prot + ((size_t)b * SS + s) * PD);
        float4* op = (float4*)(outP + ((size_t)b * SS + s) * PD);
        #pragma unroll 4
        for (int c4 = 0; c4 < PD / 4; c4++) {
            float4 p = pp[c4];
            float4 bb = bpo4s[c4];
            float4 o = make_float4(p.x + bb.x, p.y + bb.y, p.z + bb.z, p.w + bb.w);
            #pragma unroll
            for (int h = 0; h < NH; h++) {
                float4 u = U4[h][c4];
                float w = w8[h];
                o.x += w * u.x; o.y += w * u.y; o.z += w * u.z; o.w += w * u.w;
            }
            op[c4] = o;
        }
    }
    __syncthreads();

    // wp partial accumulation: thread = (chunk of 32 s, c4); rows re-read (L1/L2 hot)
    {
        int c4 = t & 31, chunk = t >> 5;
        float4 acc[NH];
        #pragma unroll
        for (int h = 0; h < NH; h++) acc[h] = make_float4(0.f, 0.f, 0.f, 0.f);

        const float4* pbase = (const float4*)(prot + ((size_t)b * SS + s0 + chunk * 32) * PD);
        #pragma unroll 4
        for (int i = 0; i < 32; i++) {
            float4 p = pbase[(size_t)i * (PD / 4) + c4];
            int ss = chunk * 32 + i;
            #pragma unroll
            for (int h = 0; h < NH; h++) {
                float e = e_s[ss][h];   // broadcast within warp
                acc[h].x += e * p.x; acc[h].y += e * p.y;
                acc[h].z += e * p.z; acc[h].w += e * p.w;
            }
        }
        #pragma unroll
        for (int h = 0; h < NH; h++)
            ((float4*)&part[chunk][h][0])[c4] = acc[h];
    }
    __syncthreads();

    // reduce 4 chunks and atomically add to global wp
    #pragma unroll
    for (int k = 0; k < 8; k++) {
        int idx = t + 128 * k;            // h*128 + c
        float v = part[0][0][idx] + part[1][0][idx] + part[2][0][idx] + part[3][0][idx];
        atomicAdd(&g_wp[b * NH * PD + idx], v);
    }
}

// ---------------------------------------------------------------------------
// Kernel E: attended_mol_features epilogue. grid=32, block=256
// ---------------------------------------------------------------------------
__global__ void k_final(const float* __restrict__ mol,
                        const float* __restrict__ Wpv, const float* __restrict__ bpv,
                        const float* __restrict__ Wmo, const float* __restrict__ bmo,
                        float* __restrict__ outM)
{
    int b = blockIdx.x, t = threadIdx.x;
    __shared__ float ap[AD];
    __shared__ float wps[NH * PD];

    #pragma unroll
    for (int k = 0; k < 4; k++) wps[t + 256 * k] = g_wp[b * NH * PD + t + 256 * k];
    __syncthreads();

    {
        int a = t, h = a >> 5;
        float acc = bpv[a];
        const float* w = Wpv + a * PD;
        const float* wpb = wps + h * PD;
        #pragma unroll 8
        for (int c = 0; c < PD; c++) acc += wpb[c] * w[c];
        ap[a] = acc;
    }
    __syncthreads();

    if (t < MD) {
        float acc = bmo[t] + mol[b * MD + t];
        const float* w = Wmo + t * AD;
        #pragma unroll 8
        for (int a = 0; a < AD; a++) acc += ap[a] * w[a];
        outM[b * MD + t] = acc;
    }
}

// ---------------------------------------------------------------------------
extern "C" void kernel_launch(void* const* d_in, const int* in_sizes, int n_in,
                              void* d_out, int out_size)
{
    const float* mol  = (const float*)d_in[0];
    const float* prot = (const float*)d_in[1];
    const float* Wq   = (const float*)d_in[2];
    const float* bq   = (const float*)d_in[3];
    const float* Wmv  = (const float*)d_in[4];
    const float* bmv  = (const float*)d_in[5];
    const float* Wpk  = (const float*)d_in[6];
    const float* bpk  = (const float*)d_in[7];
    const float* Wpv  = (const float*)d_in[8];
    const float* bpv  = (const float*)d_in[9];
    const float* Wmo  = (const float*)d_in[10];
    const float* bmo  = (const float*)d_in[11];
    const float* Wpo  = (const float*)d_in[12];
    const float* bpo  = (const float*)d_in[13];

    float* out  = (float*)d_out;
    float* outM = out;                                   // [32,128]
    float* outP = out + BB * MD;                         // [32,4096,128]
    float* outA = out + BB * MD + (size_t)BB * SS * PD;  // [32,4096]

    const float scale = 0.17677669529663687f;  // 1/sqrt(32)

    k_setup<<<BB, 256>>>(mol, Wq, bq, Wmv, bmv, Wpk, bpk, Wpo);

    dim3 gB(SS / 256, BB);
    k_scores<<<gB, 256>>>(prot);

    k_stats<<<BB * NH, 256>>>(scale);

    dim3 gD(SS / 128, BB);
    k_main<<<gD, 128>>>(prot, bpo, outP, outA, scale);

    k_final<<<BB, 256>>>(mol, Wpv, bpv, Wmo, bmo, outM);
}

// round 2
// speedup vs baseline: 1.2600x; 1.2600x over previous
#include <cuda_runtime.h>
#include <math.h>

#define BB 32
#define SS 4096
#define NH 8
#define HD 32
#define PD 128   // prot dim
#define MD 128   // mol dim
#define AD 256   // att dim

// Scratch (static device globals)
__device__ float g_e[BB * SS * NH];       // unnormalized m2p exp weights
__device__ float g_qk[BB * NH * PD];      // [b][h][c] folded query-key vector
__device__ float g_kb[BB * NH];           // folded key bias dot q
__device__ float g_U[BB * NH * PD];       // [b][h][j] p2m output basis
__device__ float g_Z[BB * NH];            // m2p partition function (atomic)
__device__ float g_wp[BB * NH * PD];      // unnormalized weighted prot feats (atomic)

// ---------------------------------------------------------------------------
// Kernel A: per-batch precompute + zero accumulators. grid=32, block=256
// ---------------------------------------------------------------------------
__global__ void k_setup(const float* __restrict__ mol,
                        const float* __restrict__ Wq,  const float* __restrict__ bq,
                        const float* __restrict__ Wmv, const float* __restrict__ bmv,
                        const float* __restrict__ Wpk, const float* __restrict__ bpk,
                        const float* __restrict__ Wpo)
{
    int b = blockIdx.x, t = threadIdx.x;
    __shared__ float sm_mol[MD];
    __shared__ float sm_q[AD];
    __shared__ float sm_v[AD];

    if (t < MD) sm_mol[t] = mol[b * MD + t];
    __syncthreads();

    {
        float aq = bq[t], av = bmv[t];
        const float* wq = Wq  + t * MD;
        const float* wv = Wmv + t * MD;
        #pragma unroll 8
        for (int c = 0; c < MD; c++) {
            float m = sm_mol[c];
            aq += m * wq[c];
            av += m * wv[c];
        }
        sm_q[t] = aq;
        sm_v[t] = av;
    }
    __syncthreads();

    #pragma unroll
    for (int k = 0; k < 4; k++) {
        int idx = t + 256 * k;
        int h = idx >> 7, c = idx & 127;
        float accq = 0.f, accu = 0.f;
        #pragma unroll
        for (int d = 0; d < HD; d++) {
            accq += Wpk[(h * HD + d) * PD + c] * sm_q[h * HD + d];
            accu += sm_v[h * HD + d] * Wpo[c * AD + h * HD + d];
        }
        g_qk[b * NH * PD + idx] = accq;
        g_U [b * NH * PD + idx] = accu;
        g_wp[b * NH * PD + idx] = 0.f;   // re-zero every launch
    }

    if (t < NH) {
        float a = 0.f;
        #pragma unroll
        for (int d = 0; d < HD; d++) a += bpk[t * HD + d] * sm_q[t * HD + d];
        g_kb[b * NH + t] = a;
        g_Z [b * NH + t] = 0.f;          // re-zero every launch
    }
}

// ---------------------------------------------------------------------------
// Kernel B (FUSED): per (b,s): scores -> local p2m softmax -> outP row;
//   unnormalized m2p exps -> g_e, block partials into g_Z / g_wp.
// grid=(SS/128, BB), block=128.
// ---------------------------------------------------------------------------
__global__ void k_fused(const float* __restrict__ prot,
                        const float* __restrict__ bpo,
                        float* __restrict__ outP,
                        float scale)
{
    int b  = blockIdx.y;
    int s0 = blockIdx.x * 128;
    int t  = threadIdx.x;

    __shared__ float4 qk4[NH][PD / 4];     // 4 KB
    __shared__ float4 U4[NH][PD / 4];      // 4 KB
    __shared__ float4 bpo4[PD / 4];        // 0.5 KB
    __shared__ float  kbs[NH];
    __shared__ float  sZ[NH];
    __shared__ float  e_s[128][NH];        // 4 KB (row = 32B, f4-aligned, broadcast reads)
    __shared__ float  w_s[128][NH];        // 4 KB
    __shared__ float  part[4][NH][PD];     // 16 KB

    {
        const float4* gq = (const float4*)(g_qk + b * NH * PD);
        const float4* gU = (const float4*)(g_U  + b * NH * PD);
        ((float4*)qk4)[t]       = gq[t];
        ((float4*)qk4)[t + 128] = gq[t + 128];
        ((float4*)U4)[t]        = gU[t];
        ((float4*)U4)[t + 128]  = gU[t + 128];
        if (t < PD / 4) bpo4[t] = ((const float4*)bpo)[t];
        if (t < NH) { kbs[t] = g_kb[b * NH + t]; sZ[t] = 0.f; }
    }
    __syncthreads();

    int s = s0 + t;

    // ---- pass 1: scores for this thread's row -------------------------------
    float sc[NH];
    #pragma unroll
    for (int h = 0; h < NH; h++) sc[h] = kbs[h];

    const float4* p4 = (const float4*)(prot + ((size_t)b * SS + s) * PD);
    #pragma unroll 8
    for (int c4 = 0; c4 < PD / 4; c4++) {
        float4 p = p4[c4];
        #pragma unroll
        for (int h = 0; h < NH; h++) {
            float4 q = qk4[h][c4];   // uniform -> broadcast
            sc[h] += p.x * q.x + p.y * q.y + p.z * q.z + p.w * q.w;
        }
    }

    // ---- p2m: local softmax over heads --------------------------------------
    {
        float mx = sc[0];
        #pragma unroll
        for (int h = 1; h < NH; h++) mx = fmaxf(mx, sc[h]);
        float w8[NH], wsum = 0.f;
        #pragma unroll
        for (int h = 0; h < NH; h++) { w8[h] = expf(sc[h] - mx); wsum += w8[h]; }
        float inv = 1.f / wsum;
        *(float4*)&w_s[t][0] = make_float4(w8[0]*inv, w8[1]*inv, w8[2]*inv, w8[3]*inv);
        *(float4*)&w_s[t][4] = make_float4(w8[4]*inv, w8[5]*inv, w8[6]*inv, w8[7]*inv);
    }

    // ---- m2p: unnormalized exps (no max needed; |sc*scale| <~ 4) ------------
    {
        float e8[NH];
        #pragma unroll
        for (int h = 0; h < NH; h++) e8[h] = expf(sc[h] * scale);
        float4 eA = make_float4(e8[0], e8[1], e8[2], e8[3]);
        float4 eB = make_float4(e8[4], e8[5], e8[6], e8[7]);
        *(float4*)&e_s[t][0] = eA;
        *(float4*)&e_s[t][4] = eB;
        float4* ge = (float4*)(g_e + ((size_t)b * SS + s) * NH);
        ge[0] = eA; ge[1] = eB;

        // per-warp Z partials -> shared atomics
        #pragma unroll
        for (int h = 0; h < NH; h++) {
            float v = e8[h];
            #pragma unroll
            for (int o = 16; o; o >>= 1) v += __shfl_xor_sync(~0u, v, o);
            if ((t & 31) == 0) atomicAdd(&sZ[h], v);
        }
    }
    __syncthreads();

    if (t < NH) atomicAdd(&g_Z[b * NH + t], sZ[t]);

    // ---- pass 2 (transposed): outP rows + wp partials -----------------------
    {
        int c4 = t & 31, chunk = t >> 5;
        float4 Uc[NH];
        #pragma unroll
        for (int h = 0; h < NH; h++) Uc[h] = U4[h][c4];
        float4 bb = bpo4[c4];
        float4 acc[NH];
        #pragma unroll
        for (int h = 0; h < NH; h++) acc[h] = make_float4(0.f, 0.f, 0.f, 0.f);

        const float4* pb = (const float4*)(prot + ((size_t)b * SS + s0 + chunk * 32) * PD) + c4;
        float4*       ob = (float4*)(outP + ((size_t)b * SS + s0 + chunk * 32) * PD) + c4;

        #pragma unroll 4
        for (int i = 0; i < 32; i++) {
            int row = chunk * 32 + i;
            float4 p  = pb[(size_t)i * (PD / 4)];        // L1 hit (read in pass 1)
            float4 wA = *(const float4*)&w_s[row][0];    // broadcast
            float4 wB = *(const float4*)&w_s[row][4];
            float4 eA = *(const float4*)&e_s[row][0];
            float4 eB = *(const float4*)&e_s[row][4];

            float4 o = make_float4(p.x + bb.x, p.y + bb.y, p.z + bb.z, p.w + bb.w);
            o.x += wA.x*Uc[0].x + wA.y*Uc[1].x + wA.z*Uc[2].x + wA.w*Uc[3].x
                 + wB.x*Uc[4].x + wB.y*Uc[5].x + wB.z*Uc[6].x + wB.w*Uc[7].x;
            o.y += wA.x*Uc[0].y + wA.y*Uc[1].y + wA.z*Uc[2].y + wA.w*Uc[3].y
                 + wB.x*Uc[4].y + wB.y*Uc[5].y + wB.z*Uc[6].y + wB.w*Uc[7].y;
            o.z += wA.x*Uc[0].z + wA.y*Uc[1].z + wA.z*Uc[2].z + wA.w*Uc[3].z
                 + wB.x*Uc[4].z + wB.y*Uc[5].z + wB.z*Uc[6].z + wB.w*Uc[7].z;
            o.w += wA.x*Uc[0].w + wA.y*Uc[1].w + wA.z*Uc[2].w + wA.w*Uc[3].w
                 + wB.x*Uc[4].w + wB.y*Uc[5].w + wB.z*Uc[6].w + wB.w*Uc[7].w;
            ob[(size_t)i * (PD / 4)] = o;

            acc[0].x += eA.x*p.x; acc[0].y += eA.x*p.y; acc[0].z += eA.x*p.z; acc[0].w += eA.x*p.w;
            acc[1].x += eA.y*p.x; acc[1].y += eA.y*p.y; acc[1].z += eA.y*p.z; acc[1].w += eA.y*p.w;
            acc[2].x += eA.z*p.x; acc[2].y += eA.z*p.y; acc[2].z += eA.z*p.z; acc[2].w += eA.z*p.w;
            acc[3].x += eA.w*p.x; acc[3].y += eA.w*p.y; acc[3].z += eA.w*p.z; acc[3].w += eA.w*p.w;
            acc[4].x += eB.x*p.x; acc[4].y += eB.x*p.y; acc[4].z += eB.x*p.z; acc[4].w += eB.x*p.w;
            acc[5].x += eB.y*p.x; acc[5].y += eB.y*p.y; acc[5].z += eB.y*p.z; acc[5].w += eB.y*p.w;
            acc[6].x += eB.z*p.x; acc[6].y += eB.z*p.y; acc[6].z += eB.z*p.z; acc[6].w += eB.z*p.w;
            acc[7].x += eB.w*p.x; acc[7].y += eB.w*p.y; acc[7].z += eB.w*p.z; acc[7].w += eB.w*p.w;
        }

        #pragma unroll
        for (int h = 0; h < NH; h++)
            ((float4*)&part[chunk][h][0])[c4] = acc[h];
    }
    __syncthreads();

    // reduce chunk partials -> global wp (one atomic per element)
    #pragma unroll
    for (int k = 0; k < NH; k++) {
        int idx = t + 128 * k;   // = h*128 + c
        float v = part[0][0][idx] + part[1][0][idx] + part[2][0][idx] + part[3][0][idx];
        atomicAdd(&g_wp[b * NH * PD + idx], v);
    }
}

// ---------------------------------------------------------------------------
// Kernel C: avg attention weights = (1/8) * sum_h e/Z.  grid=(16,32), blk=256
// ---------------------------------------------------------------------------
__global__ void k_avg(float* __restrict__ outA)
{
    int b = blockIdx.y, t = threadIdx.x;
    int s = blockIdx.x * 256 + t;
    __shared__ float zinv[NH];
    if (t < NH) zinv[t] = 1.f / g_Z[b * NH + t];
    __syncthreads();

    const float4* ge = (const float4*)(g_e + ((size_t)b * SS + s) * NH);
    float4 e0 = ge[0], e1 = ge[1];
    float sum = e0.x*zinv[0] + e0.y*zinv[1] + e0.z*zinv[2] + e0.w*zinv[3]
              + e1.x*zinv[4] + e1.y*zinv[5] + e1.z*zinv[6] + e1.w*zinv[7];
    outA[(size_t)b * SS + s] = sum * 0.125f;
}

// ---------------------------------------------------------------------------
// Kernel D: attended_mol_features epilogue. grid=32, block=256
// ---------------------------------------------------------------------------
__global__ void k_final(const float* __restrict__ mol,
                        const float* __restrict__ Wpv, const float* __restrict__ bpv,
                        const float* __restrict__ Wmo, const float* __restrict__ bmo,
                        float* __restrict__ outM)
{
    int b = blockIdx.x, t = threadIdx.x;
    __shared__ float ap[AD];
    __shared__ float wps[NH * PD];
    __shared__ float zin[NH];

    if (t < NH) zin[t] = 1.f / g_Z[b * NH + t];
    __syncthreads();

    #pragma unroll
    for (int k = 0; k < 4; k++) {
        int idx = t + 256 * k;
        wps[idx] = g_wp[b * NH * PD + idx] * zin[idx >> 7];
    }
    __syncthreads();

    {
        int a = t, h = a >> 5;
        float acc = bpv[a];
        const float* w   = Wpv + a * PD;
        const float* wpb = wps + h * PD;
        #pragma unroll 8
        for (int c = 0; c < PD; c++) acc += wpb[c] * w[c];
        ap[a] = acc;
    }
    __syncthreads();

    if (t < MD) {
        float acc = bmo[t] + mol[b * MD + t];
        const float* w = Wmo + t * AD;
        #pragma unroll 8
        for (int a = 0; a < AD; a++) acc += ap[a] * w[a];
        outM[b * MD + t] = acc;
    }
}

// ---------------------------------------------------------------------------
extern "C" void kernel_launch(void* const* d_in, const int* in_sizes, int n_in,
                              void* d_out, int out_size)
{
    const float* mol  = (const float*)d_in[0];
    const float* prot = (const float*)d_in[1];
    const float* Wq   = (const float*)d_in[2];
    const float* bq   = (const float*)d_in[3];
    const float* Wmv  = (const float*)d_in[4];
    const float* bmv  = (const float*)d_in[5];
    const float* Wpk  = (const float*)d_in[6];
    const float* bpk  = (const float*)d_in[7];
    const float* Wpv  = (const float*)d_in[8];
    const float* bpv  = (const float*)d_in[9];
    const float* Wmo  = (const float*)d_in[10];
    const float* bmo  = (const float*)d_in[11];
    const float* Wpo  = (const float*)d_in[12];
    const float* bpo  = (const float*)d_in[13];

    float* out  = (float*)d_out;
    float* outM = out;                                   // [32,128]
    float* outP = out + BB * MD;                         // [32,4096,128]
    float* outA = out + BB * MD + (size_t)BB * SS * PD;  // [32,4096]

    const float scale = 0.17677669529663687f;  // 1/sqrt(32)

    k_setup<<<BB, 256>>>(mol, Wq, bq, Wmv, bmv, Wpk, bpk, Wpo);

    dim3 gF(SS / 128, BB);
    k_fused<<<gF, 128>>>(prot, bpo, outP, scale);

    dim3 gA(SS / 256, BB);
    k_avg<<<gA, 256>>>(outA);

    k_final<<<BB, 256>>>(mol, Wpv, bpv, Wmo, bmo, outM);
}

// round 3
// speedup vs baseline: 1.6533x; 1.3121x over previous
#include <cuda_runtime.h>
#include <math.h>

#define BB 32
#define SS 4096
#define NH 8
#define HD 32
#define PD 128   // prot dim
#define MD 128   // mol dim
#define AD 256   // att dim

// Scratch (static device globals)
__device__ float g_e[BB * SS * NH];       // unnormalized m2p exp weights
__device__ float g_qk[BB * NH * PD];      // folded query-key vector
__device__ float g_kb[BB * NH];           // folded key bias dot q
__device__ float g_U[BB * NH * PD];       // p2m output basis
__device__ float g_Z[BB * NH];            // m2p partition function (atomic)
__device__ float g_wp[BB * NH * PD];      // unnormalized weighted prot feats (atomic)
__device__ float g_ap[BB * AD];           // attended_prot pre-output

// ---------------------------------------------------------------------------
// Kernel A: per-batch precompute, fully coalesced. grid=32, block=256
// ---------------------------------------------------------------------------
__global__ void k_setup(const float* __restrict__ mol,
                        const float* __restrict__ Wq,  const float* __restrict__ bq,
                        const float* __restrict__ Wmv, const float* __restrict__ bmv,
                        const float* __restrict__ Wpk, const float* __restrict__ bpk,
                        const float* __restrict__ Wpo)
{
    int b = blockIdx.x, t = threadIdx.x;
    int wid = t >> 5, lane = t & 31;
    __shared__ float4 sm_mol4[MD / 4];
    __shared__ float  sm_q[AD];
    __shared__ float  sm_v[AD];

    if (t < MD / 4) sm_mol4[t] = ((const float4*)(mol + b * MD))[t];
    __syncthreads();

    // mol_q / mol_v: warp-per-output, coalesced float4 row reads + shuffle reduce
    {
        float4 m = sm_mol4[lane];
        for (int o = wid; o < AD; o += 8) {
            float4 wq = ((const float4*)(Wq  + o * MD))[lane];
            float4 wv = ((const float4*)(Wmv + o * MD))[lane];
            float pq = m.x*wq.x + m.y*wq.y + m.z*wq.z + m.w*wq.w;
            float pv = m.x*wv.x + m.y*wv.y + m.z*wv.z + m.w*wv.w;
            #pragma unroll
            for (int off = 16; off; off >>= 1) {
                pq += __shfl_xor_sync(~0u, pq, off);
                pv += __shfl_xor_sync(~0u, pv, off);
            }
            if (lane == 0) {
                sm_q[o] = pq + bq[o];
                sm_v[o] = pv + bmv[o];
            }
        }
    }
    __syncthreads();

    // qk[b][h][c]: c consecutive across threads -> coalesced
    #pragma unroll
    for (int k = 0; k < 4; k++) {
        int idx = t + 256 * k;
        int h = idx >> 7, c = idx & 127;
        float accq = 0.f;
        #pragma unroll
        for (int d = 0; d < HD; d++)
            accq += Wpk[(h * HD + d) * PD + c] * sm_q[h * HD + d];
        g_qk[b * NH * PD + idx] = accq;
        g_wp[b * NH * PD + idx] = 0.f;   // re-zero every launch
    }

    // U[b][h][c]: warp w == head h, lane = d, coalesced 128B reads
    {
        int h = wid;
        float vv = sm_v[h * HD + lane];
        #pragma unroll 2
        for (int c = 0; c < PD; c++) {
            float p = Wpo[c * AD + h * HD + lane] * vv;
            #pragma unroll
            for (int off = 16; off; off >>= 1) p += __shfl_xor_sync(~0u, p, off);
            if (lane == 0) g_U[b * NH * PD + h * PD + c] = p;
        }
    }

    if (t < NH) {
        float a = 0.f;
        #pragma unroll
        for (int d = 0; d < HD; d++) a += bpk[t * HD + d] * sm_q[t * HD + d];
        g_kb[b * NH + t] = a;
        g_Z [b * NH + t] = 0.f;          // re-zero every launch
    }
}

// ---------------------------------------------------------------------------
// Kernel B (FUSED): scores + p2m softmax + outP + unnormalized m2p/Z/wp.
// grid=(SS/128, BB), block=128.  Pass-1 prot reads staged via smem (coalesced).
// ---------------------------------------------------------------------------
__global__ void __launch_bounds__(128) k_fused(const float* __restrict__ prot,
                                               const float* __restrict__ bpo,
                                               float* __restrict__ outP,
                                               float scale)
{
    int b  = blockIdx.y;
    int s0 = blockIdx.x * 128;
    int t  = threadIdx.x;

    __shared__ float4 qk4[NH][PD / 4];     // 4 KB
    __shared__ float4 U4[NH][PD / 4];      // 4 KB
    __shared__ float4 bpo4[PD / 4];        // 0.5 KB
    __shared__ float  kbs[NH];
    __shared__ float  sZ[NH];
    __shared__ float  e_s[128][NH];        // 4 KB
    __shared__ float  w_s[128][NH];        // 4 KB
    // stage (pass1) and part (pass2) never live simultaneously -> alias. 18 KB.
    __shared__ float4 stage_part[128 * 9];
    float4* stage  = stage_part;                 // tile[row*9 + c4l], pad-9: conflict-free
    float*  part   = (float*)stage_part;         // [4][NH][PD] = 16 KB

    {
        const float4* gq = (const float4*)(g_qk + b * NH * PD);
        const float4* gU = (const float4*)(g_U  + b * NH * PD);
        ((float4*)qk4)[t]       = gq[t];
        ((float4*)qk4)[t + 128] = gq[t + 128];
        ((float4*)U4)[t]        = gU[t];
        ((float4*)U4)[t + 128]  = gU[t + 128];
        if (t < PD / 4) bpo4[t] = ((const float4*)bpo)[t];
        if (t < NH) { kbs[t] = g_kb[b * NH + t]; sZ[t] = 0.f; }
    }
    __syncthreads();

    int s = s0 + t;

    // ---- pass 1: scores via smem-staged tiles (4 chunks of 32 floats/row) ---
    float sc[NH];
    #pragma unroll
    for (int h = 0; h < NH; h++) sc[h] = kbs[h];

    const float4* pblk = (const float4*)(prot + ((size_t)b * SS + s0) * PD);
    int r0 = t >> 3, c4l = t & 7;

    #pragma unroll
    for (int cc = 0; cc < 4; cc++) {
        #pragma unroll
        for (int it = 0; it < 8; it++) {
            int row = it * 16 + r0;
            stage[row * 9 + c4l] = pblk[(size_t)row * (PD / 4) + cc * 8 + c4l];
        }
        __syncthreads();
        #pragma unroll
        for (int j = 0; j < 8; j++) {
            float4 p = stage[t * 9 + j];
            int c4 = cc * 8 + j;
            #pragma unroll
            for (int h = 0; h < NH; h++) {
                float4 q = qk4[h][c4];
                sc[h] += p.x * q.x + p.y * q.y + p.z * q.z + p.w * q.w;
            }
        }
        __syncthreads();
    }

    // ---- p2m: local softmax over heads --------------------------------------
    {
        float mx = sc[0];
        #pragma unroll
        for (int h = 1; h < NH; h++) mx = fmaxf(mx, sc[h]);
        float w8[NH], wsum = 0.f;
        #pragma unroll
        for (int h = 0; h < NH; h++) { w8[h] = expf(sc[h] - mx); wsum += w8[h]; }
        float inv = 1.f / wsum;
        *(float4*)&w_s[t][0] = make_float4(w8[0]*inv, w8[1]*inv, w8[2]*inv, w8[3]*inv);
        *(float4*)&w_s[t][4] = make_float4(w8[4]*inv, w8[5]*inv, w8[6]*inv, w8[7]*inv);
    }

    // ---- m2p: unnormalized exps (|sc*scale| small; no max needed) -----------
    {
        float e8[NH];
        #pragma unroll
        for (int h = 0; h < NH; h++) e8[h] = expf(sc[h] * scale);
        float4 eA = make_float4(e8[0], e8[1], e8[2], e8[3]);
        float4 eB = make_float4(e8[4], e8[5], e8[6], e8[7]);
        *(float4*)&e_s[t][0] = eA;
        *(float4*)&e_s[t][4] = eB;
        float4* ge = (float4*)(g_e + ((size_t)b * SS + s) * NH);
        ge[0] = eA; ge[1] = eB;

        #pragma unroll
        for (int h = 0; h < NH; h++) {
            float v = e8[h];
            #pragma unroll
            for (int o = 16; o; o >>= 1) v += __shfl_xor_sync(~0u, v, o);
            if ((t & 31) == 0) atomicAdd(&sZ[h], v);
        }
    }
    __syncthreads();

    if (t < NH) atomicAdd(&g_Z[b * NH + t], sZ[t]);

    // ---- pass 2 (transposed, coalesced): outP rows + wp partials ------------
    {
        int c4 = t & 31, chunk = t >> 5;
        float4 Uc[NH];
        #pragma unroll
        for (int h = 0; h < NH; h++) Uc[h] = U4[h][c4];
        float4 bb = bpo4[c4];
        float4 acc[NH];
        #pragma unroll
        for (int h = 0; h < NH; h++) acc[h] = make_float4(0.f, 0.f, 0.f, 0.f);

        const float4* pb = (const float4*)(prot + ((size_t)b * SS + s0 + chunk * 32) * PD) + c4;
        float4*       ob = (float4*)(outP + ((size_t)b * SS + s0 + chunk * 32) * PD) + c4;

        #pragma unroll 4
        for (int i = 0; i < 32; i++) {
            int row = chunk * 32 + i;
            float4 p  = pb[(size_t)i * (PD / 4)];
            float4 wA = *(const float4*)&w_s[row][0];
            float4 wB = *(const float4*)&w_s[row][4];
            float4 eA = *(const float4*)&e_s[row][0];
            float4 eB = *(const float4*)&e_s[row][4];

            float4 o = make_float4(p.x + bb.x, p.y + bb.y, p.z + bb.z, p.w + bb.w);
            o.x += wA.x*Uc[0].x + wA.y*Uc[1].x + wA.z*Uc[2].x + wA.w*Uc[3].x
                 + wB.x*Uc[4].x + wB.y*Uc[5].x + wB.z*Uc[6].x + wB.w*Uc[7].x;
            o.y += wA.x*Uc[0].y + wA.y*Uc[1].y + wA.z*Uc[2].y + wA.w*Uc[3].y
                 + wB.x*Uc[4].y + wB.y*Uc[5].y + wB.z*Uc[6].y + wB.w*Uc[7].y;
            o.z += wA.x*Uc[0].z + wA.y*Uc[1].z + wA.z*Uc[2].z + wA.w*Uc[3].z
                 + wB.x*Uc[4].z + wB.y*Uc[5].z + wB.z*Uc[6].z + wB.w*Uc[7].z;
            o.w += wA.x*Uc[0].w + wA.y*Uc[1].w + wA.z*Uc[2].w + wA.w*Uc[3].w
                 + wB.x*Uc[4].w + wB.y*Uc[5].w + wB.z*Uc[6].w + wB.w*Uc[7].w;
            ob[(size_t)i * (PD / 4)] = o;

            acc[0].x += eA.x*p.x; acc[0].y += eA.x*p.y; acc[0].z += eA.x*p.z; acc[0].w += eA.x*p.w;
            acc[1].x += eA.y*p.x; acc[1].y += eA.y*p.y; acc[1].z += eA.y*p.z; acc[1].w += eA.y*p.w;
            acc[2].x += eA.z*p.x; acc[2].y += eA.z*p.y; acc[2].z += eA.z*p.z; acc[2].w += eA.z*p.w;
            acc[3].x += eA.w*p.x; acc[3].y += eA.w*p.y; acc[3].z += eA.w*p.z; acc[3].w += eA.w*p.w;
            acc[4].x += eB.x*p.x; acc[4].y += eB.x*p.y; acc[4].z += eB.x*p.z; acc[4].w += eB.x*p.w;
            acc[5].x += eB.y*p.x; acc[5].y += eB.y*p.y; acc[5].z += eB.y*p.z; acc[5].w += eB.y*p.w;
            acc[6].x += eB.z*p.x; acc[6].y += eB.z*p.y; acc[6].z += eB.z*p.z; acc[6].w += eB.z*p.w;
            acc[7].x += eB.w*p.x; acc[7].y += eB.w*p.y; acc[7].z += eB.w*p.z; acc[7].w += eB.w*p.w;
        }

        __syncthreads();   // stage reads done long ago; part now safe to write
        #pragma unroll
        for (int h = 0; h < NH; h++)
            ((float4*)part)[(chunk * NH + h) * (PD / 4) + c4] = acc[h];
    }
    __syncthreads();

    #pragma unroll
    for (int k = 0; k < NH; k++) {
        int idx = t + 128 * k;
        float v = part[idx] + part[1024 + idx] + part[2048 + idx] + part[3072 + idx];
        atomicAdd(&g_wp[b * NH * PD + idx], v);
    }
}

// ---------------------------------------------------------------------------
// Kernel C: avg attention weights. grid=(16,32), block=256
// ---------------------------------------------------------------------------
__global__ void k_avg(float* __restrict__ outA)
{
    int b = blockIdx.y, t = threadIdx.x;
    int s = blockIdx.x * 256 + t;
    __shared__ float zinv[NH];
    if (t < NH) zinv[t] = 1.f / g_Z[b * NH + t];
    __syncthreads();

    const float4* ge = (const float4*)(g_e + ((size_t)b * SS + s) * NH);
    float4 e0 = ge[0], e1 = ge[1];
    float sum = e0.x*zinv[0] + e0.y*zinv[1] + e0.z*zinv[2] + e0.w*zinv[3]
              + e1.x*zinv[4] + e1.y*zinv[5] + e1.z*zinv[6] + e1.w*zinv[7];
    outA[(size_t)b * SS + s] = sum * 0.125f;
}

// ---------------------------------------------------------------------------
// Kernel D1: ap[b][a] = bpv[a] + (wp[b][h]/Z) . Wpv[a]. warp-per-output.
// grid=1024, block=256 (8192 warps)
// ---------------------------------------------------------------------------
__global__ void k_ap(const float* __restrict__ Wpv, const float* __restrict__ bpv)
{
    int t = threadIdx.x, lane = t & 31;
    int gw = blockIdx.x * 8 + (t >> 5);
    int b = gw >> 8, a = gw & 255, h = a >> 5;

    float4 w = ((const float4*)(Wpv + a * PD))[lane];
    float4 p = ((const float4*)(g_wp + b * NH * PD + h * PD))[lane];
    float acc = w.x*p.x + w.y*p.y + w.z*p.z + w.w*p.w;
    #pragma unroll
    for (int o = 16; o; o >>= 1) acc += __shfl_xor_sync(~0u, acc, o);
    if (lane == 0)
        g_ap[b * AD + a] = bpv[a] + acc / g_Z[b * NH + h];
}

// ---------------------------------------------------------------------------
// Kernel D2: outM[b][t] = bmo + mol + ap . Wmo[t]. warp-per-output.
// grid=512, block=256 (4096 warps)
// ---------------------------------------------------------------------------
__global__ void k_out(const float* __restrict__ mol,
                      const float* __restrict__ Wmo, const float* __restrict__ bmo,
                      float* __restrict__ outM)
{
    int t = threadIdx.x, lane = t & 31;
    int gw = blockIdx.x * 8 + (t >> 5);
    int b = gw >> 7, o = gw & 127;

    const float4* wr = (const float4*)(Wmo + o * AD);
    const float4* ar = (const float4*)(g_ap + b * AD);
    float4 w0 = wr[lane],      a0 = ar[lane];
    float4 w1 = wr[lane + 32], a1 = ar[lane + 32];
    float acc = w0.x*a0.x + w0.y*a0.y + w0.z*a0.z + w0.w*a0.w
              + w1.x*a1.x + w1.y*a1.y + w1.z*a1.z + w1.w*a1.w;
    #pragma unroll
    for (int off = 16; off; off >>= 1) acc += __shfl_xor_sync(~0u, acc, off);
    if (lane == 0)
        outM[b * MD + o] = bmo[o] + mol[b * MD + o] + acc;
}

// ---------------------------------------------------------------------------
extern "C" void kernel_launch(void* const* d_in, const int* in_sizes, int n_in,
                              void* d_out, int out_size)
{
    const float* mol  = (const float*)d_in[0];
    const float* prot = (const float*)d_in[1];
    const float* Wq   = (const float*)d_in[2];
    const float* bq   = (const float*)d_in[3];
    const float* Wmv  = (const float*)d_in[4];
    const float* bmv  = (const float*)d_in[5];
    const float* Wpk  = (const float*)d_in[6];
    const float* bpk  = (const float*)d_in[7];
    const float* Wpv  = (const float*)d_in[8];
    const float* bpv  = (const float*)d_in[9];
    const float* Wmo  = (const float*)d_in[10];
    const float* bmo  = (const float*)d_in[11];
    const float* Wpo  = (const float*)d_in[12];
    const float* bpo  = (const float*)d_in[13];

    float* out  = (float*)d_out;
    float* outM = out;                                   // [32,128]
    float* outP = out + BB * MD;                         // [32,4096,128]
    float* outA = out + BB * MD + (size_t)BB * SS * PD;  // [32,4096]

    const float scale = 0.17677669529663687f;  // 1/sqrt(32)

    k_setup<<<BB, 256>>>(mol, Wq, bq, Wmv, bmv, Wpk, bpk, Wpo);

    dim3 gF(SS / 128, BB);
    k_fused<<<gF, 128>>>(prot, bpo, outP, scale);

    dim3 gA(SS / 256, BB);
    k_avg<<<gA, 256>>>(outA);

    k_ap<<<1024, 256>>>(Wpv, bpv);

    k_out<<<512, 256>>>(mol, Wmo, bmo, outM);
}

// round 4
// speedup vs baseline: 2.4250x; 1.4668x over previous
#include <cuda_runtime.h>
#include <math.h>

#define BB 32
#define SS 4096
#define NH 8
#define HD 32
#define PD 128   // prot dim
#define MD 128   // mol dim
#define AD 256   // att dim

typedef unsigned long long u64;

#define FMA2(d, a, b, c) asm("fma.rn.f32x2 %0, %1, %2, %3;" : "=l"(d) : "l"(a), "l"(b), "l"(c))
#define ADD2(d, a, b)    asm("add.rn.f32x2 %0, %1, %2;"     : "=l"(d) : "l"(a), "l"(b))
#define PACK2(d, s)      asm("mov.b64 %0, {%1, %1};"        : "=l"(d) : "f"(s))
#define UNPK2(lo, hi, v) asm("mov.b64 {%0, %1}, %2;"        : "=f"(lo), "=f"(hi) : "l"(v))

// Scratch (static device globals)
__device__ float g_e[BB * SS * NH];       // unnormalized m2p exp weights
__device__ float g_q[BB * AD];            // mol_q
__device__ float g_v[BB * AD];            // mol_v
__device__ float g_qk[BB * NH * PD];      // folded query-key vector
__device__ float g_kb[BB * NH];           // folded key bias dot q
__device__ float g_U[BB * NH * PD];       // p2m output basis
__device__ float g_Z[BB * NH];            // m2p partition function (atomic)
__device__ float g_wp[BB * NH * PD];      // unnormalized weighted prot feats (atomic)
__device__ float g_ap[BB * AD];           // attended_prot pre-output

// ---------------------------------------------------------------------------
// Kernel A1: mol_q / mol_v / kb + zero accumulators. grid=32, block=256
// ---------------------------------------------------------------------------
__global__ void k_qv(const float* __restrict__ mol,
                     const float* __restrict__ Wq,  const float* __restrict__ bq,
                     const float* __restrict__ Wmv, const float* __restrict__ bmv,
                     const float* __restrict__ bpk)
{
    int b = blockIdx.x, t = threadIdx.x;
    int wid = t >> 5, lane = t & 31;
    __shared__ float4 m4[MD / 4];
    __shared__ float  sq[AD];

    if (t < MD / 4) m4[t] = ((const float4*)(mol + b * MD))[t];
    __syncthreads();

    float4 m = m4[lane];
    for (int o = wid; o < AD; o += 8) {
        float4 wq = ((const float4*)(Wq  + o * MD))[lane];
        float4 wv = ((const float4*)(Wmv + o * MD))[lane];
        float pq = m.x*wq.x + m.y*wq.y + m.z*wq.z + m.w*wq.w;
        float pv = m.x*wv.x + m.y*wv.y + m.z*wv.z + m.w*wv.w;
        #pragma unroll
        for (int off = 16; off; off >>= 1) {
            pq += __shfl_xor_sync(~0u, pq, off);
            pv += __shfl_xor_sync(~0u, pv, off);
        }
        if (lane == 0) {
            float qv = pq + bq[o], vv = pv + bmv[o];
            g_q[b * AD + o] = qv;
            g_v[b * AD + o] = vv;
            sq[o] = qv;
        }
    }

    // zero accumulators (graph-replay safe)
    #pragma unroll
    for (int k = 0; k < 4; k++) g_wp[b * NH * PD + t + 256 * k] = 0.f;
    if (t < NH) g_Z[b * NH + t] = 0.f;
    __syncthreads();

    // kb[b][h] = bpk[h].q[h]; warp h, lane d
    {
        int h = wid;
        float v = bpk[h * HD + lane] * sq[h * HD + lane];
        #pragma unroll
        for (int off = 16; off; off >>= 1) v += __shfl_xor_sync(~0u, v, off);
        if (lane == 0) g_kb[b * NH + h] = v;
    }
}

// ---------------------------------------------------------------------------
// Kernel A2: qk and U for ALL batches via smem weight tiles.
// grid=(4 c-chunks, 8 heads), block=256. All loads coalesced; smem pad-33.
// ---------------------------------------------------------------------------
__global__ void k_prep(const float* __restrict__ Wpk,
                       const float* __restrict__ Wpo)
{
    int c0 = blockIdx.x * 32, h = blockIdx.y;
    int t = threadIdx.x;

    __shared__ float wk[32][33];  // [d][c]
    __shared__ float wo[32][33];  // [c][d]
    __shared__ float qs[32][33];  // [b][d]
    __shared__ float vs[32][33];  // [b][d]

    #pragma unroll
    for (int i = 0; i < 4; i++) {
        int idx = t + 256 * i;
        int r = idx >> 5, c = idx & 31;
        wk[r][c] = Wpk[(h * HD + r) * PD + c0 + c];        // d=r, col c
        wo[r][c] = Wpo[(c0 + r) * AD + h * HD + c];        // c=r, d=c
        qs[r][c] = g_q[r * AD + h * HD + c];               // b=r, d=c
        vs[r][c] = g_v[r * AD + h * HD + c];
    }
    __syncthreads();

    #pragma unroll
    for (int rr = 0; rr < 4; rr++) {
        int b = (t >> 5) + 8 * rr, c = t & 31;
        float aq = 0.f, au = 0.f;
        #pragma unroll
        for (int d = 0; d < 32; d++) {
            aq += wk[d][c] * qs[b][d];
            au += wo[c][d] * vs[b][d];
        }
        g_qk[b * NH * PD + h * PD + c0 + c] = aq;
        g_U [b * NH * PD + h * PD + c0 + c] = au;
    }
}

// ---------------------------------------------------------------------------
// Kernel B (FUSED, packed f32x2 math): scores + p2m softmax + outP + m2p/Z/wp.
// grid=(SS/128, BB), block=128.
// ---------------------------------------------------------------------------
__global__ void __launch_bounds__(128) k_fused(const float* __restrict__ prot,
                                               const float* __restrict__ bpo,
                                               float* __restrict__ outP,
                                               float scale)
{
    int b  = blockIdx.y;
    int s0 = blockIdx.x * 128;
    int t  = threadIdx.x;

    __shared__ float4 qk4[NH][PD / 4];     // 4 KB
    __shared__ float4 U4[NH][PD / 4];      // 4 KB
    __shared__ float4 bpo4[PD / 4];        // 0.5 KB
    __shared__ float  kbs[NH];
    __shared__ float  sZ[NH];
    __shared__ float  e_s[128][NH];        // 4 KB
    __shared__ float  w_s[128][NH];        // 4 KB
    __shared__ float4 stage_part[128 * 9]; // 18 KB; stage (pass1) aliases part (pass2)
    float4* stage = stage_part;
    float*  part  = (float*)stage_part;

    {
        const float4* gq = (const float4*)(g_qk + b * NH * PD);
        const float4* gU = (const float4*)(g_U  + b * NH * PD);
        ((float4*)qk4)[t]       = gq[t];
        ((float4*)qk4)[t + 128] = gq[t + 128];
        ((float4*)U4)[t]        = gU[t];
        ((float4*)U4)[t + 128]  = gU[t + 128];
        if (t < PD / 4) bpo4[t] = ((const float4*)bpo)[t];
        if (t < NH) { kbs[t] = g_kb[b * NH + t]; sZ[t] = 0.f; }
    }
    __syncthreads();

    int s = s0 + t;

    // ---- pass 1: scores via smem-staged tiles, packed FMA -------------------
    u64 acc2[NH];
    #pragma unroll
    for (int h = 0; h < NH; h++) acc2[h] = 0ULL;

    const float4* pblk = (const float4*)(prot + ((size_t)b * SS + s0) * PD);
    int r0 = t >> 3, c4l = t & 7;

    #pragma unroll
    for (int cc = 0; cc < 4; cc++) {
        #pragma unroll
        for (int it = 0; it < 8; it++) {
            int row = it * 16 + r0;
            stage[row * 9 + c4l] = pblk[(size_t)row * (PD / 4) + cc * 8 + c4l];
        }
        __syncthreads();
        #pragma unroll
        for (int j = 0; j < 8; j++) {
            ulonglong2 p = *(const ulonglong2*)&stage[t * 9 + j];
            int c4 = cc * 8 + j;
            #pragma unroll
            for (int h = 0; h < NH; h++) {
                ulonglong2 q = *(const ulonglong2*)&qk4[h][c4];
                FMA2(acc2[h], p.x, q.x, acc2[h]);
                FMA2(acc2[h], p.y, q.y, acc2[h]);
            }
        }
        __syncthreads();
    }

    float sc[NH];
    #pragma unroll
    for (int h = 0; h < NH; h++) {
        float lo, hi;
        UNPK2(lo, hi, acc2[h]);
        sc[h] = lo + hi + kbs[h];
    }

    // ---- p2m: local softmax over heads --------------------------------------
    {
        float mx = sc[0];
        #pragma unroll
        for (int h = 1; h < NH; h++) mx = fmaxf(mx, sc[h]);
        float w8[NH], wsum = 0.f;
        #pragma unroll
        for (int h = 0; h < NH; h++) { w8[h] = __expf(sc[h] - mx); wsum += w8[h]; }
        float inv = 1.f / wsum;
        *(float4*)&w_s[t][0] = make_float4(w8[0]*inv, w8[1]*inv, w8[2]*inv, w8[3]*inv);
        *(float4*)&w_s[t][4] = make_float4(w8[4]*inv, w8[5]*inv, w8[6]*inv, w8[7]*inv);
    }

    // ---- m2p: unnormalized exps ---------------------------------------------
    {
        float e8[NH];
        #pragma unroll
        for (int h = 0; h < NH; h++) e8[h] = __expf(sc[h] * scale);
        float4 eA = make_float4(e8[0], e8[1], e8[2], e8[3]);
        float4 eB = make_float4(e8[4], e8[5], e8[6], e8[7]);
        *(float4*)&e_s[t][0] = eA;
        *(float4*)&e_s[t][4] = eB;
        float4* ge = (float4*)(g_e + ((size_t)b * SS + s) * NH);
        ge[0] = eA; ge[1] = eB;

        #pragma unroll
        for (int h = 0; h < NH; h++) {
            float v = e8[h];
            #pragma unroll
            for (int o = 16; o; o >>= 1) v += __shfl_xor_sync(~0u, v, o);
            if ((t & 31) == 0) atomicAdd(&sZ[h], v);
        }
    }
    __syncthreads();

    if (t < NH) atomicAdd(&g_Z[b * NH + t], sZ[t]);

    // ---- pass 2 (transposed, coalesced, packed): outP + wp partials ---------
    {
        int c4 = t & 31, chunk = t >> 5;
        u64 UL[NH], UH[NH], accL[NH], accH[NH];
        #pragma unroll
        for (int h = 0; h < NH; h++) {
            ulonglong2 u = *(const ulonglong2*)&U4[h][c4];
            UL[h] = u.x; UH[h] = u.y;
            accL[h] = 0ULL; accH[h] = 0ULL;
        }
        ulonglong2 bb = *(const ulonglong2*)&bpo4[c4];

        const float4* pb = (const float4*)(prot + ((size_t)b * SS + s0 + chunk * 32) * PD) + c4;
        float4*       ob = (float4*)(outP + ((size_t)b * SS + s0 + chunk * 32) * PD) + c4;

        #pragma unroll 4
        for (int i = 0; i < 32; i++) {
            int row = chunk * 32 + i;
            ulonglong2 p = *(const ulonglong2*)&pb[(size_t)i * (PD / 4)];
            float4 wA = *(const float4*)&w_s[row][0];
            float4 wB = *(const float4*)&w_s[row][4];
            float4 eA = *(const float4*)&e_s[row][0];
            float4 eB = *(const float4*)&e_s[row][4];

            u64 wp0, wp1, wp2, wp3, wp4, wp5, wp6, wp7;
            PACK2(wp0, wA.x); PACK2(wp1, wA.y); PACK2(wp2, wA.z); PACK2(wp3, wA.w);
            PACK2(wp4, wB.x); PACK2(wp5, wB.y); PACK2(wp6, wB.z); PACK2(wp7, wB.w);
            u64 ep0, ep1, ep2, ep3, ep4, ep5, ep6, ep7;
            PACK2(ep0, eA.x); PACK2(ep1, eA.y); PACK2(ep2, eA.z); PACK2(ep3, eA.w);
            PACK2(ep4, eB.x); PACK2(ep5, eB.y); PACK2(ep6, eB.z); PACK2(ep7, eB.w);

            u64 oL, oH;
            ADD2(oL, p.x, bb.x);
            ADD2(oH, p.y, bb.y);
            FMA2(oL, wp0, UL[0], oL); FMA2(oH, wp0, UH[0], oH);
            FMA2(oL, wp1, UL[1], oL); FMA2(oH, wp1, UH[1], oH);
            FMA2(oL, wp2, UL[2], oL); FMA2(oH, wp2, UH[2], oH);
            FMA2(oL, wp3, UL[3], oL); FMA2(oH, wp3, UH[3], oH);
            FMA2(oL, wp4, UL[4], oL); FMA2(oH, wp4, UH[4], oH);
            FMA2(oL, wp5, UL[5], oL); FMA2(oH, wp5, UH[5], oH);
            FMA2(oL, wp6, UL[6], oL); FMA2(oH, wp6, UH[6], oH);
            FMA2(oL, wp7, UL[7], oL); FMA2(oH, wp7, UH[7], oH);
            ulonglong2 ov; ov.x = oL; ov.y = oH;
            *(ulonglong2*)&ob[(size_t)i * (PD / 4)] = ov;

            FMA2(accL[0], ep0, p.x, accL[0]); FMA2(accH[0], ep0, p.y, accH[0]);
            FMA2(accL[1], ep1, p.x, accL[1]); FMA2(accH[1], ep1, p.y, accH[1]);
            FMA2(accL[2], ep2, p.x, accL[2]); FMA2(accH[2], ep2, p.y, accH[2]);
            FMA2(accL[3], ep3, p.x, accL[3]); FMA2(accH[3], ep3, p.y, accH[3]);
            FMA2(accL[4], ep4, p.x, accL[4]); FMA2(accH[4], ep4, p.y, accH[4]);
            FMA2(accL[5], ep5, p.x, accL[5]); FMA2(accH[5], ep5, p.y, accH[5]);
            FMA2(accL[6], ep6, p.x, accL[6]); FMA2(accH[6], ep6, p.y, accH[6]);
            FMA2(accL[7], ep7, p.x, accL[7]); FMA2(accH[7], ep7, p.y, accH[7]);
        }

        __syncthreads();   // stage reads long done; part safe to write
        float4* part4 = (float4*)part;
        #pragma unroll
        for (int h = 0; h < NH; h++) {
            ulonglong2 av; av.x = accL[h]; av.y = accH[h];
            *(ulonglong2*)&part4[(chunk * NH + h) * (PD / 4) + c4] = av;
        }
    }
    __syncthreads();

    #pragma unroll
    for (int k = 0; k < NH; k++) {
        int idx = t + 128 * k;
        float v = part[idx] + part[1024 + idx] + part[2048 + idx] + part[3072 + idx];
        atomicAdd(&g_wp[b * NH * PD + idx], v);
    }
}

// ---------------------------------------------------------------------------
// Kernel C: avg attention weights. grid=(16,32), block=256
// ---------------------------------------------------------------------------
__global__ void k_avg(float* __restrict__ outA)
{
    int b = blockIdx.y, t = threadIdx.x;
    int s = blockIdx.x * 256 + t;
    __shared__ float zinv[NH];
    if (t < NH) zinv[t] = 1.f / g_Z[b * NH + t];
    __syncthreads();

    const float4* ge = (const float4*)(g_e + ((size_t)b * SS + s) * NH);
    float4 e0 = ge[0], e1 = ge[1];
    float sum = e0.x*zinv[0] + e0.y*zinv[1] + e0.z*zinv[2] + e0.w*zinv[3]
              + e1.x*zinv[4] + e1.y*zinv[5] + e1.z*zinv[6] + e1.w*zinv[7];
    outA[(size_t)b * SS + s] = sum * 0.125f;
}

// ---------------------------------------------------------------------------
// Kernel D1: ap = bpv + (wp/Z).Wpv. warp-per-output, grid=1024, block=256
// ---------------------------------------------------------------------------
__global__ void k_ap(const float* __restrict__ Wpv, const float* __restrict__ bpv)
{
    int t = threadIdx.x, lane = t & 31;
    int gw = blockIdx.x * 8 + (t >> 5);
    int b = gw >> 8, a = gw & 255, h = a >> 5;

    float4 w = ((const float4*)(Wpv + a * PD))[lane];
    float4 p = ((const float4*)(g_wp + b * NH * PD + h * PD))[lane];
    float acc = w.x*p.x + w.y*p.y + w.z*p.z + w.w*p.w;
    #pragma unroll
    for (int o = 16; o; o >>= 1) acc += __shfl_xor_sync(~0u, acc, o);
    if (lane == 0)
        g_ap[b * AD + a] = bpv[a] + acc / g_Z[b * NH + h];
}

// ---------------------------------------------------------------------------
// Kernel D2: outM = bmo + mol + ap.Wmo. warp-per-output, grid=512, block=256
// ---------------------------------------------------------------------------
__global__ void k_out(const float* __restrict__ mol,
                      const float* __restrict__ Wmo, const float* __restrict__ bmo,
                      float* __restrict__ outM)
{
    int t = threadIdx.x, lane = t & 31;
    int gw = blockIdx.x * 8 + (t >> 5);
    int b = gw >> 7, o = gw & 127;

    const float4* wr = (const float4*)(Wmo + o * AD);
    const float4* ar = (const float4*)(g_ap + b * AD);
    float4 w0 = wr[lane],      a0 = ar[lane];
    float4 w1 = wr[lane + 32], a1 = ar[lane + 32];
    float acc = w0.x*a0.x + w0.y*a0.y + w0.z*a0.z + w0.w*a0.w
              + w1.x*a1.x + w1.y*a1.y + w1.z*a1.z + w1.w*a1.w;
    #pragma unroll
    for (int off = 16; off; off >>= 1) acc += __shfl_xor_sync(~0u, acc, off);
    if (lane == 0)
        outM[b * MD + o] = bmo[o] + mol[b * MD + o] + acc;
}

// ---------------------------------------------------------------------------
extern "C" void kernel_launch(void* const* d_in, const int* in_sizes, int n_in,
                              void* d_out, int out_size)
{
    const float* mol  = (const float*)d_in[0];
    const float* prot = (const float*)d_in[1];
    const float* Wq   = (const float*)d_in[2];
    const float* bq   = (const float*)d_in[3];
    const float* Wmv  = (const float*)d_in[4];
    const float* bmv  = (const float*)d_in[5];
    const float* Wpk  = (const float*)d_in[6];
    const float* bpk  = (const float*)d_in[7];
    const float* Wpv  = (const float*)d_in[8];
    const float* bpv  = (const float*)d_in[9];
    const float* Wmo  = (const float*)d_in[10];
    const float* bmo  = (const float*)d_in[11];
    const float* Wpo  = (const float*)d_in[12];
    const float* bpo  = (const float*)d_in[13];

    float* out  = (float*)d_out;
    float* outM = out;                                   // [32,128]
    float* outP = out + BB * MD;                         // [32,4096,128]
    float* outA = out + BB * MD + (size_t)BB * SS * PD;  // [32,4096]

    const float scale = 0.17677669529663687f;  // 1/sqrt(32)

    k_qv<<<BB, 256>>>(mol, Wq, bq, Wmv, bmv, bpk);

    dim3 gP(4, NH);
    k_prep<<<gP, 256>>>(Wpk, Wpo);

    dim3 gF(SS / 128, BB);
    k_fused<<<gF, 128>>>(prot, bpo, outP, scale);

    dim3 gA(SS / 256, BB);
    k_avg<<<gA, 256>>>(outA);

    k_ap<<<1024, 256>>>(Wpv, bpv);

    k_out<<<512, 256>>>(mol, Wmo, bmo, outM);
}